// round 12
// baseline (speedup 1.0000x reference)
#include <cuda_runtime.h>
#include <cuda_bf16.h>

#define T_STEPS 4096
#define M_BATCH 512
#define D_IN    11
#define NH      51
#define G4      204
#define A1S     64      // x[11] | h1[51] | pad2
#define A2S     112     // h1[51] | h2[51] | pad10  (K padded to 112 -> 14 ul2 per half)
#define KH1U    8       // ulonglong2 per L1 K-half (32 floats)
#define KH2U    14      // ulonglong2 per L2 K-half (56 floats)
#define THREADS 288     // 9 warps: gates on warps 0-6 (tid<204), epi on warps 7-8 (tid>=224)
#define EPI0    224
#define BLOCKS  128

__device__ __forceinline__ float tanha(float x) {
    float y; asm("tanh.approx.f32 %0, %1;" : "=f"(y) : "f"(x)); return y;
}
__device__ __forceinline__ float siga(float x) {
    return fmaf(0.5f, tanha(0.5f * x), 0.5f);
}
__device__ __forceinline__ unsigned long long fma2(unsigned long long a,
                                                   unsigned long long b,
                                                   unsigned long long c) {
    unsigned long long d;
    asm("fma.rn.f32x2 %0, %1, %2, %3;" : "=l"(d) : "l"(a), "l"(b), "l"(c));
    return d;
}
__device__ __forceinline__ unsigned long long pack2(float lo, float hi) {
    unsigned long long r;
    asm("mov.b64 %0, {%1, %2};" : "=l"(r) : "f"(lo), "f"(hi));
    return r;
}
__device__ __forceinline__ float sum2(unsigned long long v) {
    float lo, hi;
    asm("mov.b64 {%0, %1}, %2;" : "=f"(lo), "=f"(hi) : "l"(v));
    return lo + hi;
}

// ---- gate GEMMs for one group (2 rows), executed by gate threads only ----
#define DO_GEMMS(g, okL1, okL2)                                                \
    {                                                                          \
        if (okL1) {                                                            \
            unsigned long long a00 = pack2(b1lo, 0.f), a01 = pack2(b1lo, 0.f); \
            unsigned long long a10 = pack2(b1hi, 0.f), a11 = pack2(b1hi, 0.f); \
            const ulonglong2* p0 = (const ulonglong2*)&A1[g][0][0] + hf * KH1U;\
            const ulonglong2* p1 = (const ulonglong2*)&A1[g][1][0] + hf * KH1U;\
            _Pragma("unroll")                                                  \
            for (int q = 0; q < KH1U; ++q) {                                   \
                ulonglong2 u = p0[q], v = p1[q];                               \
                a00 = fma2(w1[0][2*q], u.x, a00); a00 = fma2(w1[0][2*q+1], u.y, a00); \
                a01 = fma2(w1[0][2*q], v.x, a01); a01 = fma2(w1[0][2*q+1], v.y, a01); \
                a10 = fma2(w1[1][2*q], u.x, a10); a10 = fma2(w1[1][2*q+1], u.y, a10); \
                a11 = fma2(w1[1][2*q], v.x, a11); a11 = fma2(w1[1][2*q+1], v.y, a11); \
            }                                                                  \
            *(float2*)&GS1[g][hf][0][c0] = make_float2(sum2(a00), sum2(a10));  \
            *(float2*)&GS1[g][hf][1][c0] = make_float2(sum2(a01), sum2(a11));  \
        }                                                                      \
        if (okL2) {                                                            \
            unsigned long long a00 = pack2(b2lo, 0.f), a01 = pack2(b2lo, 0.f); \
            unsigned long long a10 = pack2(b2hi, 0.f), a11 = pack2(b2hi, 0.f); \
            const ulonglong2* p0 = (const ulonglong2*)&A2[g][0][0] + hf * KH2U;\
            const ulonglong2* p1 = (const ulonglong2*)&A2[g][1][0] + hf * KH2U;\
            _Pragma("unroll")                                                  \
            for (int q = 0; q < KH2U; ++q) {                                   \
                ulonglong2 u = p0[q], v = p1[q];                               \
                a00 = fma2(w2[0][2*q], u.x, a00); a00 = fma2(w2[0][2*q+1], u.y, a00); \
                a01 = fma2(w2[0][2*q], v.x, a01); a01 = fma2(w2[0][2*q+1], v.y, a01); \
                a10 = fma2(w2[1][2*q], u.x, a10); a10 = fma2(w2[1][2*q+1], u.y, a10); \
                a11 = fma2(w2[1][2*q], v.x, a11); a11 = fma2(w2[1][2*q+1], v.y, a11); \
            }                                                                  \
            *(float2*)&GS2[g][hf][0][c0] = make_float2(sum2(a00), sum2(a10));  \
            *(float2*)&GS2[g][hf][1][c0] = make_float2(sum2(a01), sum2(a11));  \
        }                                                                      \
    }

// ---- cell updates for one group (epi threads; up to 2 slots each) ----
#define DO_EPI(g, cst1, cst2, okH1, okH2)                                      \
    {                                                                          \
        _Pragma("unroll")                                                      \
        for (int s2 = 0; s2 < 2; ++s2) if (sok[s2]) {                          \
            const int r = sr[s2], n = sn[s2];                                  \
            if (okH1) {                                                        \
                float gi = GS1[g][0][r][n]        + GS1[g][1][r][n];           \
                float gf = GS1[g][0][r][NH+n]     + GS1[g][1][r][NH+n];        \
                float gg = GS1[g][0][r][2*NH+n]   + GS1[g][1][r][2*NH+n];      \
                float go = GS1[g][0][r][3*NH+n]   + GS1[g][1][r][3*NH+n];      \
                cst1[s2] = siga(gf) * cst1[s2] + siga(gi) * tanha(gg);         \
                float h = siga(go) * tanha(cst1[s2]);                          \
                A1[g][r][D_IN + n] = h;                                        \
                A2[g][r][n]        = h;                                        \
            }                                                                  \
            if (okH2) {                                                        \
                float gi = GS2[g][0][r][n]        + GS2[g][1][r][n];           \
                float gf = GS2[g][0][r][NH+n]     + GS2[g][1][r][NH+n];        \
                float gg = GS2[g][0][r][2*NH+n]   + GS2[g][1][r][2*NH+n];      \
                float go = GS2[g][0][r][3*NH+n]   + GS2[g][1][r][3*NH+n];      \
                cst2[s2] = siga(gf) * cst2[s2] + siga(gi) * tanha(gg);         \
                float h = siga(go) * tanha(cst2[s2]);                          \
                A2[g][r][NH + n] = h;                                          \
                PO[g][r][n] = h * swl[s2];                                     \
            }                                                                  \
        }                                                                      \
    }

#define DO_REDUCE(g, step)                                                     \
    {                                                                          \
        int ew = et >> 5, lane = et & 31;                                      \
        float v = PO[g][ew][lane] + PO[g][ew][32 + lane];                      \
        _Pragma("unroll")                                                      \
        for (int off = 16; off > 0; off >>= 1)                                 \
            v += __shfl_down_sync(0xffffffffu, v, off);                        \
        if (lane == 0)                                                         \
            out[(mbase + 2 * (g) + ew) * T_STEPS + (step)] = v + bl;           \
    }

__global__ void __launch_bounds__(THREADS, 1)
lstm2_persistent_kernel(const float* __restrict__ x,
                        const float* __restrict__ Wih1, const float* __restrict__ Whh1,
                        const float* __restrict__ bih1, const float* __restrict__ bhh1,
                        const float* __restrict__ Wih2, const float* __restrict__ Whh2,
                        const float* __restrict__ bih2, const float* __restrict__ bhh2,
                        const float* __restrict__ Wlin, const float* __restrict__ blin,
                        float* __restrict__ out)
{
    __shared__ float A1[2][2][A1S];           // [group][row][.]
    __shared__ float A2[2][2][A2S];
    __shared__ float GS1[2][2][2][G4];        // [group][hf][row][col]
    __shared__ float GS2[2][2][2][G4];
    __shared__ float PO[2][2][64];

    const int tid   = threadIdx.x;
    const int mbase = blockIdx.x * 4;
    const bool is_gate = (tid < G4);
    const bool is_epi  = (tid >= EPI0);
    const int  et      = tid - EPI0;          // epi index 0..63 (when is_epi)

    int hf = 0, c0 = 0;
    if (is_gate) {
        hf = (tid >= 102) ? 1 : 0;
        int cp = tid - 102 * hf;              // 0..101
        c0 = 2 * cp;
    }

    // ---- register weights: 2 cols x K-half, packed f32x2 ----
    unsigned long long w1[2][2 * KH1U];       // 32 u64
    unsigned long long w2[2][2 * KH2U];       // 56 u64
    #pragma unroll
    for (int c = 0; c < 2; ++c) {
        #pragma unroll
        for (int i = 0; i < 2 * KH1U; ++i) w1[c][i] = 0ull;
        #pragma unroll
        for (int i = 0; i < 2 * KH2U; ++i) w2[c][i] = 0ull;
    }
    float b1lo = 0.f, b1hi = 0.f, b2lo = 0.f, b2hi = 0.f;
    if (is_gate) {
        #pragma unroll
        for (int c = 0; c < 2; ++c) {
            const int col = c0 + c;
            #pragma unroll
            for (int i = 0; i < 2 * KH1U; ++i) {       // K-half of padded 64
                int k = hf * 32 + 2 * i;
                float lo = 0.f, hi = 0.f;
                if (k < D_IN)            lo = Wih1[col * D_IN + k];
                else if (k < D_IN + NH)  lo = Whh1[col * NH + (k - D_IN)];
                int k1 = k + 1;
                if (k1 < D_IN)           hi = Wih1[col * D_IN + k1];
                else if (k1 < D_IN + NH) hi = Whh1[col * NH + (k1 - D_IN)];
                w1[c][i] = pack2(lo, hi);
            }
            #pragma unroll
            for (int i = 0; i < 2 * KH2U; ++i) {       // K-half of padded 112
                int k = hf * 56 + 2 * i;
                float lo = 0.f, hi = 0.f;
                if (k < NH)              lo = Wih2[col * NH + k];
                else if (k < 2 * NH)     lo = Whh2[col * NH + (k - NH)];
                int k1 = k + 1;
                if (k1 < NH)             hi = Wih2[col * NH + k1];
                else if (k1 < 2 * NH)    hi = Whh2[col * NH + (k1 - NH)];
                w2[c][i] = pack2(lo, hi);
            }
        }
        if (hf == 0) {
            b1lo = bih1[c0] + bhh1[c0];     b1hi = bih1[c0+1] + bhh1[c0+1];
            b2lo = bih2[c0] + bhh2[c0];     b2hi = bih2[c0+1] + bhh2[c0+1];
        }
    }

    // ---- epi setup: up to 2 cell slots; states per group/layer ----
    int sn[2] = {0, 0}, sr[2] = {0, 0};
    bool sok[2] = {false, false};
    float swl[2] = {0.f, 0.f};
    float cA1[2] = {0.f, 0.f}, cA2[2] = {0.f, 0.f};
    float cB1[2] = {0.f, 0.f}, cB2[2] = {0.f, 0.f};
    if (is_epi) {
        #pragma unroll
        for (int s2 = 0; s2 < 2; ++s2) {
            int s = et + 64 * s2;
            if (s < 2 * NH) {
                sok[s2] = true;
                sr[s2]  = (s >= NH) ? 1 : 0;
                sn[s2]  = s - NH * sr[s2];
                swl[s2] = Wlin[sn[s2]];
            }
        }
    }
    const float bl = blin[0];

    // ---- init shared ----
    for (int i = tid; i < 2 * 2 * A1S; i += THREADS) (&A1[0][0][0])[i] = 0.f;
    for (int i = tid; i < 2 * 2 * A2S; i += THREADS) (&A2[0][0][0])[i] = 0.f;
    for (int i = tid; i < 2 * 2 * 64;  i += THREADS) (&PO[0][0][0])[i] = 0.f;
    if (tid < 44) {                                  // x(0) for both groups
        int g = tid / 22, rem = tid % 22, r = rem / 11, k = rem % 11;
        A1[g][r][k] = x[(mbase + 2 * g + r) * D_IN + k];
    }
    __syncthreads();

    for (int i = 0; i <= T_STEPS + 2; ++i) {
        // ========== PHASE A: gates group 0 | epi group 1 ==========
        if (is_gate) {
            const bool okL1 = (i < T_STEPS);
            const bool okL2 = (i >= 1 && i <= T_STEPS);
            DO_GEMMS(0, okL1, okL2);
        } else if (is_epi) {
            float xv = 0.f;
            if (et < 22 && i < T_STEPS)
                xv = x[(i * M_BATCH + mbase + 2 + et / 11) * D_IN + (et % 11)];
            if (i >= 3) DO_REDUCE(1, i - 3);
            {
                const bool okH1 = (i >= 1 && i <= T_STEPS);
                const bool okH2 = (i >= 2 && i <= T_STEPS + 1);
                DO_EPI(1, cB1, cB2, okH1, okH2);
            }
            if (et < 22 && i < T_STEPS)
                A1[1][et / 11][et % 11] = xv;          // x_B(i) for gates-B(i)
        }
        __syncthreads();

        // ========== PHASE B: gates group 1 | epi group 0 ==========
        if (is_gate) {
            const bool okL1 = (i < T_STEPS);
            const bool okL2 = (i >= 1 && i <= T_STEPS);
            DO_GEMMS(1, okL1, okL2);
        } else if (is_epi) {
            float xv = 0.f;
            if (et < 22 && i + 1 < T_STEPS)
                xv = x[((i + 1) * M_BATCH + mbase + et / 11) * D_IN + (et % 11)];
            if (i >= 2 && i <= T_STEPS + 1) DO_REDUCE(0, i - 2);
            {
                const bool okH1 = (i < T_STEPS);
                const bool okH2 = (i >= 1 && i <= T_STEPS);
                DO_EPI(0, cA1, cA2, okH1, okH2);
            }
            if (et < 22 && i + 1 < T_STEPS)
                A1[0][et / 11][et % 11] = xv;          // x_A(i+1) for gates-A(i+1)
        }
        __syncthreads();
    }
}

extern "C" void kernel_launch(void* const* d_in, const int* in_sizes, int n_in,
                              void* d_out, int out_size) {
    const float* x    = (const float*)d_in[0];
    const float* Wih1 = (const float*)d_in[1];
    const float* Whh1 = (const float*)d_in[2];
    const float* bih1 = (const float*)d_in[3];
    const float* bhh1 = (const float*)d_in[4];
    const float* Wih2 = (const float*)d_in[5];
    const float* Whh2 = (const float*)d_in[6];
    const float* bih2 = (const float*)d_in[7];
    const float* bhh2 = (const float*)d_in[8];
    const float* Wlin = (const float*)d_in[9];
    const float* blin = (const float*)d_in[10];
    float* out = (float*)d_out;

    lstm2_persistent_kernel<<<BLOCKS, THREADS>>>(
        x, Wih1, Whh1, bih1, bhh1, Wih2, Whh2, bih2, bhh2, Wlin, blin, out);
}

// round 16
// speedup vs baseline: 1.8590x; 1.8590x over previous
#include <cuda_runtime.h>
#include <cuda_bf16.h>

#define T_STEPS 4096
#define M_BATCH 512
#define D_IN    11
#define NH      51
#define G4      204
#define A1S     64      // x[11] | h1[51] | pad2   (padded K=64, half=32 floats=16 u64)
#define A2S     104     // h1[51] | h2[51] | pad2  (padded K=104, half=52 floats=26 u64)
#define THREADS 256     // warps 0-6: gates (204 active), warp 7: epilogue
#define EPI0    224
#define BLOCKS  128     // 128 * 4 rows = 512

__device__ __forceinline__ float tanha(float x) {
    float y; asm("tanh.approx.f32 %0, %1;" : "=f"(y) : "f"(x)); return y;
}
__device__ __forceinline__ float siga(float x) {
    return fmaf(0.5f, tanha(0.5f * x), 0.5f);
}
__device__ __forceinline__ unsigned long long fma2(unsigned long long a,
                                                   unsigned long long b,
                                                   unsigned long long c) {
    unsigned long long d;
    asm("fma.rn.f32x2 %0, %1, %2, %3;" : "=l"(d) : "l"(a), "l"(b), "l"(c));
    return d;
}
__device__ __forceinline__ unsigned long long pack2(float lo, float hi) {
    unsigned long long r;
    asm("mov.b64 %0, {%1, %2};" : "=l"(r) : "f"(lo), "f"(hi));
    return r;
}
__device__ __forceinline__ float sum2(unsigned long long v) {
    float lo, hi;
    asm("mov.b64 {%0, %1}, %2;" : "=f"(lo), "=f"(hi) : "l"(v));
    return lo + hi;
}

// ---- gate GEMMs for one group (2 rows); gate threads only ----
#define DO_GEMMS(g, okL1, okL2)                                                \
    {                                                                          \
        if (okL1) {                                                            \
            unsigned long long a00 = pack2(b1lo, 0.f), a01 = pack2(b1lo, 0.f); \
            unsigned long long a10 = pack2(b1hi, 0.f), a11 = pack2(b1hi, 0.f); \
            const ulonglong2* p0 = (const ulonglong2*)&A1[g][0][0] + hf * 8;   \
            const ulonglong2* p1 = (const ulonglong2*)&A1[g][1][0] + hf * 8;   \
            _Pragma("unroll")                                                  \
            for (int q = 0; q < 8; ++q) {                                      \
                ulonglong2 u = p0[q], v = p1[q];                               \
                a00 = fma2(w1[0][2*q], u.x, a00); a00 = fma2(w1[0][2*q+1], u.y, a00); \
                a01 = fma2(w1[0][2*q], v.x, a01); a01 = fma2(w1[0][2*q+1], v.y, a01); \
                a10 = fma2(w1[1][2*q], u.x, a10); a10 = fma2(w1[1][2*q+1], u.y, a10); \
                a11 = fma2(w1[1][2*q], v.x, a11); a11 = fma2(w1[1][2*q+1], v.y, a11); \
            }                                                                  \
            *(float2*)&GS1[g][hf][0][c0] = make_float2(sum2(a00), sum2(a10));  \
            *(float2*)&GS1[g][hf][1][c0] = make_float2(sum2(a01), sum2(a11));  \
        }                                                                      \
        if (okL2) {                                                            \
            unsigned long long a00 = pack2(b2lo, 0.f), a01 = pack2(b2lo, 0.f); \
            unsigned long long a10 = pack2(b2hi, 0.f), a11 = pack2(b2hi, 0.f); \
            const ulonglong2* p0 = (const ulonglong2*)&A2[g][0][0] + hf * 13;  \
            const ulonglong2* p1 = (const ulonglong2*)&A2[g][1][0] + hf * 13;  \
            _Pragma("unroll")                                                  \
            for (int q = 0; q < 13; ++q) {                                     \
                ulonglong2 u = p0[q], v = p1[q];                               \
                a00 = fma2(w2[0][2*q], u.x, a00); a00 = fma2(w2[0][2*q+1], u.y, a00); \
                a01 = fma2(w2[0][2*q], v.x, a01); a01 = fma2(w2[0][2*q+1], v.y, a01); \
                a10 = fma2(w2[1][2*q], u.x, a10); a10 = fma2(w2[1][2*q+1], u.y, a10); \
                a11 = fma2(w2[1][2*q], v.x, a11); a11 = fma2(w2[1][2*q+1], v.y, a11); \
            }                                                                  \
            *(float2*)&GS2[g][hf][0][c0] = make_float2(sum2(a00), sum2(a10));  \
            *(float2*)&GS2[g][hf][1][c0] = make_float2(sum2(a01), sum2(a11));  \
        }                                                                      \
    }

// ---- cell updates for one group; epi warp, 4 slots/thread ----
#define DO_EPI(g, cst1, cst2, okH1, okH2)                                      \
    {                                                                          \
        _Pragma("unroll")                                                      \
        for (int s4 = 0; s4 < 4; ++s4) if (sok[s4]) {                          \
            const int r = sr[s4], n = sn[s4];                                  \
            if (okH1) {                                                        \
                float gi = GS1[g][0][r][n]        + GS1[g][1][r][n];           \
                float gf = GS1[g][0][r][NH+n]     + GS1[g][1][r][NH+n];        \
                float gg = GS1[g][0][r][2*NH+n]   + GS1[g][1][r][2*NH+n];      \
                float go = GS1[g][0][r][3*NH+n]   + GS1[g][1][r][3*NH+n];      \
                cst1[s4] = siga(gf) * cst1[s4] + siga(gi) * tanha(gg);         \
                float h = siga(go) * tanha(cst1[s4]);                          \
                A1[g][r][D_IN + n] = h;                                        \
                A2[g][r][n]        = h;                                        \
            }                                                                  \
            if (okH2) {                                                        \
                float gi = GS2[g][0][r][n]        + GS2[g][1][r][n];           \
                float gf = GS2[g][0][r][NH+n]     + GS2[g][1][r][NH+n];        \
                float gg = GS2[g][0][r][2*NH+n]   + GS2[g][1][r][2*NH+n];      \
                float go = GS2[g][0][r][3*NH+n]   + GS2[g][1][r][3*NH+n];      \
                cst2[s4] = siga(gf) * cst2[s4] + siga(gi) * tanha(gg);         \
                float h = siga(go) * tanha(cst2[s4]);                          \
                A2[g][r][NH + n] = h;                                          \
                PO[g][r][n] = h * swl[s4];                                     \
            }                                                                  \
        }                                                                      \
    }

// ---- PO reduce for one group (both rows) by the single epi warp ----
#define DO_REDUCE(g, step)                                                     \
    {                                                                          \
        _Pragma("unroll")                                                      \
        for (int rr = 0; rr < 2; ++rr) {                                       \
            float v = PO[g][rr][et] + PO[g][rr][32 + et];                      \
            _Pragma("unroll")                                                  \
            for (int off = 16; off > 0; off >>= 1)                             \
                v += __shfl_down_sync(0xffffffffu, v, off);                    \
            if (et == 0)                                                       \
                out[(mbase + 2 * (g) + rr) * T_STEPS + (step)] = v + bl;       \
        }                                                                      \
    }

__global__ void __launch_bounds__(THREADS, 1)
lstm2_persistent_kernel(const float* __restrict__ x,
                        const float* __restrict__ Wih1, const float* __restrict__ Whh1,
                        const float* __restrict__ bih1, const float* __restrict__ bhh1,
                        const float* __restrict__ Wih2, const float* __restrict__ Whh2,
                        const float* __restrict__ bih2, const float* __restrict__ bhh2,
                        const float* __restrict__ Wlin, const float* __restrict__ blin,
                        float* __restrict__ out)
{
    __shared__ float A1[2][2][A1S];           // [group][row][.]
    __shared__ float A2[2][2][A2S];
    __shared__ float GS1[2][2][2][G4];        // [group][hf][row][col]
    __shared__ float GS2[2][2][2][G4];
    __shared__ float PO[2][2][64];

    const int tid   = threadIdx.x;
    const int mbase = blockIdx.x * 4;
    const bool is_gate = (tid < G4);
    const bool is_epi  = (tid >= EPI0);
    const int  et      = tid - EPI0;          // 0..31 when epi

    int hf = 0, c0 = 0;
    if (is_gate) {
        hf = (tid >= 102) ? 1 : 0;
        c0 = 2 * (tid - 102 * hf);            // 0,2,..,202
    }

    // ---- register weights: 2 cols x K-half (packed f32x2) ----
    unsigned long long w1[2][16];             // 32 u64 = 64 regs
    unsigned long long w2[2][26];             // 52 u64 = 104 regs
    #pragma unroll
    for (int c = 0; c < 2; ++c) {
        #pragma unroll
        for (int i = 0; i < 16; ++i) w1[c][i] = 0ull;
        #pragma unroll
        for (int i = 0; i < 26; ++i) w2[c][i] = 0ull;
    }
    float b1lo = 0.f, b1hi = 0.f, b2lo = 0.f, b2hi = 0.f;
    if (is_gate) {
        #pragma unroll
        for (int c = 0; c < 2; ++c) {
            const int col = c0 + c;
            #pragma unroll
            for (int i = 0; i < 16; ++i) {            // half of padded K=64
                int k = hf * 32 + 2 * i;
                float lo = 0.f, hi = 0.f;
                if (k < D_IN)            lo = Wih1[col * D_IN + k];
                else if (k < D_IN + NH)  lo = Whh1[col * NH + (k - D_IN)];
                int k1 = k + 1;
                if (k1 < D_IN)           hi = Wih1[col * D_IN + k1];
                else if (k1 < D_IN + NH) hi = Whh1[col * NH + (k1 - D_IN)];
                w1[c][i] = pack2(lo, hi);
            }
            #pragma unroll
            for (int i = 0; i < 26; ++i) {            // half of padded K=104
                int k = hf * 52 + 2 * i;
                float lo = 0.f, hi = 0.f;
                if (k < NH)              lo = Wih2[col * NH + k];
                else if (k < 2 * NH)     lo = Whh2[col * NH + (k - NH)];
                int k1 = k + 1;
                if (k1 < NH)             hi = Wih2[col * NH + k1];
                else if (k1 < 2 * NH)    hi = Whh2[col * NH + (k1 - NH)];
                w2[c][i] = pack2(lo, hi);
            }
        }
        if (hf == 0) {
            b1lo = bih1[c0] + bhh1[c0];     b1hi = bih1[c0+1] + bhh1[c0+1];
            b2lo = bih2[c0] + bhh2[c0];     b2hi = bih2[c0+1] + bhh2[c0+1];
        }
    }

    // ---- epi warp setup: 4 cell slots/thread ----
    int sn[4] = {0,0,0,0}, sr[4] = {0,0,0,0};
    bool sok[4] = {false,false,false,false};
    float swl[4] = {0.f,0.f,0.f,0.f};
    float cA1[4] = {0.f,0.f,0.f,0.f}, cA2[4] = {0.f,0.f,0.f,0.f};
    float cB1[4] = {0.f,0.f,0.f,0.f}, cB2[4] = {0.f,0.f,0.f,0.f};
    if (is_epi) {
        #pragma unroll
        for (int s4 = 0; s4 < 4; ++s4) {
            int s = et + 32 * s4;
            if (s < 2 * NH) {
                sok[s4] = true;
                sr[s4]  = (s >= NH) ? 1 : 0;
                sn[s4]  = s - NH * sr[s4];
                swl[s4] = Wlin[sn[s4]];
            }
        }
    }
    const float bl = blin[0];

    // ---- init shared ----
    for (int i = tid; i < 2 * 2 * A1S; i += THREADS) (&A1[0][0][0])[i] = 0.f;
    for (int i = tid; i < 2 * 2 * A2S; i += THREADS) (&A2[0][0][0])[i] = 0.f;
    for (int i = tid; i < 2 * 2 * 64;  i += THREADS) (&PO[0][0][0])[i] = 0.f;
    if (tid < 44) {                                   // x(0) both groups
        int g = tid / 22, rem = tid % 22, r = rem / 11, k = rem % 11;
        A1[g][r][k] = x[(mbase + 2 * g + r) * D_IN + k];
    }
    __syncthreads();

    for (int i = 0; i <= T_STEPS + 2; ++i) {
        // ========== PHASE A: gates group 0 | epi group 1 ==========
        if (is_gate) {
            const bool okL1 = (i < T_STEPS);
            const bool okL2 = (i >= 1 && i <= T_STEPS);
            DO_GEMMS(0, okL1, okL2);
        } else if (is_epi) {
            float xv = 0.f;
            if (et < 22 && i < T_STEPS)
                xv = x[(i * M_BATCH + mbase + 2 + et / 11) * D_IN + (et % 11)];
            if (i >= 3) DO_REDUCE(1, i - 3);
            {
                const bool okH1 = (i >= 1 && i <= T_STEPS);
                const bool okH2 = (i >= 2 && i <= T_STEPS + 1);
                DO_EPI(1, cB1, cB2, okH1, okH2);
            }
            if (et < 22 && i < T_STEPS)
                A1[1][et / 11][et % 11] = xv;          // x_B(i) for gates-B(i)
        }
        __syncthreads();

        // ========== PHASE B: gates group 1 | epi group 0 ==========
        if (is_gate) {
            const bool okL1 = (i < T_STEPS);
            const bool okL2 = (i >= 1 && i <= T_STEPS);
            DO_GEMMS(1, okL1, okL2);
        } else if (is_epi) {
            float xv = 0.f;
            if (et < 22 && i + 1 < T_STEPS)
                xv = x[((i + 1) * M_BATCH + mbase + et / 11) * D_IN + (et % 11)];
            if (i >= 2 && i <= T_STEPS + 1) DO_REDUCE(0, i - 2);
            {
                const bool okH1 = (i < T_STEPS);
                const bool okH2 = (i >= 1 && i <= T_STEPS);
                DO_EPI(0, cA1, cA2, okH1, okH2);
            }
            if (et < 22 && i + 1 < T_STEPS)
                A1[0][et / 11][et % 11] = xv;          // x_A(i+1) for gates-A(i+1)
        }
        __syncthreads();
    }
}

extern "C" void kernel_launch(void* const* d_in, const int* in_sizes, int n_in,
                              void* d_out, int out_size) {
    const float* x    = (const float*)d_in[0];
    const float* Wih1 = (const float*)d_in[1];
    const float* Whh1 = (const float*)d_in[2];
    const float* bih1 = (const float*)d_in[3];
    const float* bhh1 = (const float*)d_in[4];
    const float* Wih2 = (const float*)d_in[5];
    const float* Whh2 = (const float*)d_in[6];
    const float* bih2 = (const float*)d_in[7];
    const float* bhh2 = (const float*)d_in[8];
    const float* Wlin = (const float*)d_in[9];
    const float* blin = (const float*)d_in[10];
    float* out = (float*)d_out;

    lstm2_persistent_kernel<<<BLOCKS, THREADS>>>(
        x, Wih1, Whh1, bih1, bhh1, Wih2, Whh2, bih2, bhh2, Wlin, blin, out);
}